// round 9
// baseline (speedup 1.0000x reference)
#include <cuda_runtime.h>
#include <mma.h>
#include <cstdint>
#include <math.h>

using namespace nvcuda;

constexpr int B_ = 64;
constexpr int N_ = 1024;
constexpr int D_ = 512;
constexpr int K_ = 64;
constexpr int C_ = K_ + N_;                      // 1088
constexpr long OUT_ELEMS = (long)B_ * K_ * D_;
constexpr long DOTS_OFF  = OUT_ELEMS;

#define TEMP_INV (1.0f / 0.07f)

__device__ float g_shat[K_ * D_];                // tf32-rounded normalized slots
__device__ float g_sninv[K_];                    // exact slot inverse norms
__device__ float g_S[K_ * K_];                   // exact slot-slot cosines
__device__ float g_attn[(long)B_ * K_ * C_];     // tf32-rounded attn weights

__device__ __forceinline__ float to_tf32(float x) {
    asm("cvt.rna.tf32.f32 %0, %1;" : "=f"(x) : "f"(x));
    return x;
}
__device__ __forceinline__ uint32_t smem_u32(const void* p) {
    uint32_t a;
    asm("{ .reg .u64 t; cvta.to.shared.u64 t, %1; cvt.u32.u64 %0, t; }" : "=r"(a) : "l"(p));
    return a;
}
__device__ __forceinline__ void cp16(uint32_t dst, const void* src) {
    asm volatile("cp.async.cg.shared.global [%0], [%1], 16;" :: "r"(dst), "l"(src));
}
__device__ __forceinline__ void cp_commit() {
    asm volatile("cp.async.commit_group;" ::: "memory");
}

// ---------------------------------------------------------------------------
// K1: normalize slots -> g_shat (tf32-rounded) + g_sninv (exact)
// ---------------------------------------------------------------------------
__global__ void k_slot_norm(const float* __restrict__ slot) {
    int i = blockIdx.x, t = threadIdx.x;
    float v[4]; float ss = 0.f;
#pragma unroll
    for (int j = 0; j < 4; j++) { v[j] = slot[i * D_ + t + j * 128]; ss += v[j] * v[j]; }
#pragma unroll
    for (int o = 16; o; o >>= 1) ss += __shfl_xor_sync(0xffffffffu, ss, o);
    __shared__ float red[4];
    if ((t & 31) == 0) red[t >> 5] = ss;
    __syncthreads();
    float inv = 1.f / fmaxf(sqrtf(red[0] + red[1] + red[2] + red[3]), 1e-12f);
#pragma unroll
    for (int j = 0; j < 4; j++) g_shat[i * D_ + t + j * 128] = to_tf32(v[j] * inv);
    if (t == 0) g_sninv[i] = inv;
}

// ---------------------------------------------------------------------------
// K2: S = norm(slot) @ norm(slot)^T, exact fp32 from raw slot + sninv
// ---------------------------------------------------------------------------
__global__ void k_slot_S(const float* __restrict__ slot) {
    int i = blockIdx.x, j = threadIdx.x;
    const float4* a = (const float4*)(slot + i * D_);
    const float4* b = (const float4*)(slot + j * D_);
    float acc = 0.f;
#pragma unroll 8
    for (int d = 0; d < D_ / 4; d++) {
        float4 x = a[d], y = b[d];
        acc += x.x * y.x + x.y * y.y + x.z * y.z + x.w * y.w;
    }
    g_S[i * K_ + j] = acc * g_sninv[i] * g_sninv[j];
}

// nop: aligns ncu's captured (4th) launch onto k_dots
__global__ void k_nop() {}

// ---------------------------------------------------------------------------
// K3: dots key-part. CTA: 128 keys x 64 slots, 256 thr / 8 warps,
// warp tile 32x32 (c[2][2], 32 accum regs). cp.async 3-stage, kc=16.
// __launch_bounds__(256,3) -> <=85 regs -> 3 CTA/SM = 24 warps/SM.
// ---------------------------------------------------------------------------
constexpr int SD_KINV = 0;                        // 128 floats
constexpr int SD_PIPE = 128;
constexpr int SD_ASZ  = 128 * 20;                 // 2560 floats per stage (A)
constexpr int SD_BSZ  = 64 * 20;                  // 1280 floats per stage (B)
constexpr int SD_STG  = SD_ASZ + SD_BSZ;          // 3840
constexpr int SD_CS   = SD_PIPE;                  // epilogue union (8448 <= 11520)
constexpr int SD_TOT  = SD_PIPE + 3 * SD_STG;     // 11648 floats = 46592 B

__global__ __launch_bounds__(256, 3) void k_dots(const float* __restrict__ key,
                                                 float* __restrict__ dout) {
    extern __shared__ float smf[];
    const uint32_t sb = smem_u32(smf);
    const int t = threadIdx.x, wid = t >> 5;
    const int b = blockIdx.y, n0blk = blockIdx.x * 128;
    const float* keyb = key + (long)b * N_ * D_;

    const int m0 = (wid >> 1) * 32;   // key offset of warp tile
    const int n0 = (wid & 1) * 32;    // slot offset of warp tile

    wmma::fragment<wmma::accumulator, 16, 16, 8, float> c[2][2];
#pragma unroll
    for (int i = 0; i < 2; i++)
#pragma unroll
        for (int j = 0; j < 2; j++) wmma::fill_fragment(c[i][j], 0.f);

    float ss = 0.f;
    const int rr = t >> 1;            // norm: pair of threads per key row

    auto issue = [&](int jc) {
        int s = jc % 3;
        uint32_t ab = sb + (SD_PIPE + s * SD_STG) * 4;
        uint32_t bb = ab + SD_ASZ * 4;
        const float* gA = keyb + (long)n0blk * D_ + jc * 16;
        // A: key[128 x 16] = 512 f4, 2 per thread
#pragma unroll
        for (int q = 0; q < 2; q++) {
            int idx = t + 256 * q, row = idx >> 2, f = idx & 3;
            cp16(ab + (row * 20 + f * 4) * 4, gA + (long)row * D_ + f * 4);
        }
        // B: shat[64 x 16] = 256 f4, 1 per thread
        {
            int row = t >> 2, f = t & 3;
            cp16(bb + (row * 20 + f * 4) * 4, g_shat + row * D_ + jc * 16 + f * 4);
        }
        cp_commit();
    };

    issue(0);
    issue(1);

    for (int jc = 0; jc < 32; jc++) {
        if (jc + 1 < 32) asm volatile("cp.async.wait_group 1;" ::: "memory");
        else             asm volatile("cp.async.wait_group 0;" ::: "memory");
        __syncthreads();
        if (jc + 2 < 32) issue(jc + 2);
        const int s = jc % 3;
        float* As = smf + SD_PIPE + s * SD_STG;
        float* Bs = As + SD_ASZ;
        // norm: thread pair (2rr, 2rr+1) owns key row rr; 2 f4 each (rotated)
#pragma unroll
        for (int cc = 0; cc < 2; cc++) {
            int c2 = (rr + cc) & 1;
            float4 v = *(const float4*)(As + rr * 20 + ((t & 1) * 2 + c2) * 4);
            ss += v.x * v.x + v.y * v.y + v.z * v.z + v.w * v.w;
        }
#pragma unroll
        for (int kk = 0; kk < 2; kk++) {
            int k0 = kk * 8;
            wmma::fragment<wmma::matrix_a, 16, 16, 8, wmma::precision::tf32, wmma::row_major> a0, a1;
            wmma::fragment<wmma::matrix_b, 16, 16, 8, wmma::precision::tf32, wmma::col_major> b0, b1;
            wmma::load_matrix_sync(a0, As + (m0)      * 20 + k0, 20);
            wmma::load_matrix_sync(a1, As + (m0 + 16) * 20 + k0, 20);
            wmma::load_matrix_sync(b0, Bs + (n0)      * 20 + k0, 20);
            wmma::load_matrix_sync(b1, Bs + (n0 + 16) * 20 + k0, 20);
            wmma::mma_sync(c[0][0], a0, b0, c[0][0]);
            wmma::mma_sync(c[0][1], a0, b1, c[0][1]);
            wmma::mma_sync(c[1][0], a1, b0, c[1][0]);
            wmma::mma_sync(c[1][1], a1, b1, c[1][1]);
        }
    }

    // key inverse norms: reduce thread pairs
    ss += __shfl_xor_sync(0xffffffffu, ss, 1);
    if ((t & 1) == 0) smf[SD_KINV + rr] = 1.f / fmaxf(sqrtf(ss), 1e-12f);
    __syncthreads();     // pipeline consumption done; safe to overwrite with CS

    // C fragments -> smem col-major Cs[slot][key] (ld 132)
#pragma unroll
    for (int i = 0; i < 2; i++)
#pragma unroll
        for (int j = 0; j < 2; j++)
            wmma::store_matrix_sync(smf + SD_CS + (n0 + 16 * j) * 132 + (m0 + 16 * i),
                                    c[i][j], 132, wmma::mem_col_major);
    __syncthreads();

    // write dots key-part: thread -> slot s = t>>2, key quarter kg = t&3
    {
        int s = t >> 2, kg = t & 3;
        const float* src = smf + SD_CS + s * 132 + kg * 32;
        const float* kv  = smf + SD_KINV + kg * 32;
        float* dst = dout + DOTS_OFF + (long)b * K_ * C_ + (long)s * C_ + K_ + n0blk + kg * 32;
#pragma unroll
        for (int g = 0; g < 8; g++) {
            float4 w = {src[g * 4 + 0] * kv[g * 4 + 0], src[g * 4 + 1] * kv[g * 4 + 1],
                        src[g * 4 + 2] * kv[g * 4 + 2], src[g * 4 + 3] * kv[g * 4 + 3]};
            *(float4*)(dst + g * 4) = w;
        }
    }
}

// ---------------------------------------------------------------------------
// K4: row softmax with block-causal mask -> g_attn (tf32-rounded);
// slot-slot dots -> output.
// ---------------------------------------------------------------------------
__global__ __launch_bounds__(256) void k_softmax(float* __restrict__ dout) {
    int row  = (blockIdx.x * blockDim.x + threadIdx.x) >> 5;
    int lane = threadIdx.x & 31;
    int b = row >> 6, i = row & 63;

    float* drow = dout + DOTS_OFF + (long)b * K_ * C_ + (long)i * C_;

    float sv[2], kvv[32];
    float m = -1e30f;
#pragma unroll
    for (int r = 0; r < 2; r++) {
        int c = lane + r * 32;
        float s = g_S[i * K_ + c];
        sv[r] = s;
        drow[c] = s;
        if (c < i) m = fmaxf(m, s);
    }
#pragma unroll
    for (int r = 0; r < 32; r++) {
        float v = drow[K_ + lane + r * 32];
        kvv[r] = v;
        m = fmaxf(m, v);
    }
#pragma unroll
    for (int o = 16; o; o >>= 1) m = fmaxf(m, __shfl_xor_sync(0xffffffffu, m, o));

    float sum = 0.f, es[2], ek[32];
#pragma unroll
    for (int r = 0; r < 2; r++) {
        int c = lane + r * 32;
        float x = (c < i) ? __expf((sv[r] - m) * TEMP_INV) : 0.f;
        es[r] = x; sum += x;
    }
#pragma unroll
    for (int r = 0; r < 32; r++) {
        float x = __expf((kvv[r] - m) * TEMP_INV);
        ek[r] = x; sum += x;
    }
#pragma unroll
    for (int o = 16; o; o >>= 1) sum += __shfl_xor_sync(0xffffffffu, sum, o);

    float inv = 1.f / (sum * (1.f + 1e-7f));
    float* at = g_attn + (long)row * C_;
#pragma unroll
    for (int r = 0; r < 2; r++) at[lane + r * 32] = to_tf32(es[r] * inv);
#pragma unroll
    for (int r = 0; r < 32; r++) at[K_ + lane + r * 32] = to_tf32(ek[r] * inv);
}

// ---------------------------------------------------------------------------
// K5: out = attn_n @ [slots; key_b]. CTA: 64 slots x 128 d, 256 thr / 8 warps,
// warp tile 32x32. cp.async 3-stage, kc=16 (68 chunks). Direct global store.
// ---------------------------------------------------------------------------
constexpr int SO_ASZ = 64 * 20;                   // 1280 floats per stage
constexpr int SO_BSZ = 16 * 132;                  // 2112
constexpr int SO_STG = SO_ASZ + SO_BSZ;           // 3392
constexpr int SO_TOT = 3 * SO_STG;                // 10176 floats = 40704 B

__global__ __launch_bounds__(256, 3) void k_out(const float* __restrict__ slot,
                                                const float* __restrict__ key,
                                                float* __restrict__ dout) {
    extern __shared__ float smf[];
    const uint32_t sb = smem_u32(smf);
    const int t = threadIdx.x, wid = t >> 5;
    const int b = blockIdx.y, d0 = blockIdx.x * 128;
    const float* keyb  = key + (long)b * N_ * D_;
    const float* attnb = g_attn + (long)b * K_ * C_;

    const int m0 = (wid & 1) * 32;    // slot offset
    const int n0 = (wid >> 1) * 32;   // d offset

    wmma::fragment<wmma::accumulator, 16, 16, 8, float> c[2][2];
#pragma unroll
    for (int i = 0; i < 2; i++)
#pragma unroll
        for (int j = 0; j < 2; j++) wmma::fill_fragment(c[i][j], 0.f);

    auto issue = [&](int jc) {
        int s = jc % 3;
        uint32_t ab = sb + (s * SO_STG) * 4;
        uint32_t bb = ab + SO_ASZ * 4;
        // A: attn[64 x 16] = 256 f4, 1 per thread
        {
            int row = t >> 2, f = t & 3;
            cp16(ab + (row * 20 + f * 4) * 4, attnb + (long)row * C_ + jc * 16 + f * 4);
        }
        // B: V[16 x 128] = 512 f4, 2 per thread
#pragma unroll
        for (int q = 0; q < 2; q++) {
            int idx = t + 256 * q, row = idx >> 5, f = idx & 31;
            int cc = jc * 16 + row;
            const float* src = (cc < K_) ? (slot + (long)cc * D_ + d0 + f * 4)
                                         : (keyb + (long)(cc - K_) * D_ + d0 + f * 4);
            cp16(bb + (row * 132 + f * 4) * 4, src);
        }
        cp_commit();
    };

    issue(0);
    issue(1);

    for (int jc = 0; jc < 68; jc++) {
        if (jc + 1 < 68) asm volatile("cp.async.wait_group 1;" ::: "memory");
        else             asm volatile("cp.async.wait_group 0;" ::: "memory");
        __syncthreads();
        if (jc + 2 < 68) issue(jc + 2);
        const int s = jc % 3;
        float* As = smf + s * SO_STG;
        float* Bs = As + SO_ASZ;
#pragma unroll
        for (int kk = 0; kk < 2; kk++) {
            int k0 = kk * 8;
            wmma::fragment<wmma::matrix_a, 16, 16, 8, wmma::precision::tf32, wmma::row_major> a0, a1;
            wmma::fragment<wmma::matrix_b, 16, 16, 8, wmma::precision::tf32, wmma::row_major> b0, b1;
            wmma::load_matrix_sync(a0, As + (m0)      * 20 + k0, 20);
            wmma::load_matrix_sync(a1, As + (m0 + 16) * 20 + k0, 20);
            wmma::load_matrix_sync(b0, Bs + k0 * 132 + n0,      132);
            wmma::load_matrix_sync(b1, Bs + k0 * 132 + n0 + 16, 132);
            wmma::mma_sync(c[0][0], a0, b0, c[0][0]);
            wmma::mma_sync(c[0][1], a0, b1, c[0][1]);
            wmma::mma_sync(c[1][0], a1, b0, c[1][0]);
            wmma::mma_sync(c[1][1], a1, b1, c[1][1]);
        }
    }

    // direct global store: out[b][slot][d]
#pragma unroll
    for (int i = 0; i < 2; i++)
#pragma unroll
        for (int j = 0; j < 2; j++) {
            float* gp = dout + (long)b * K_ * D_ + (long)(m0 + 16 * i) * D_ + d0 + n0 + 16 * j;
            wmma::store_matrix_sync(gp, c[i][j], D_, wmma::mem_row_major);
        }
}

// ---------------------------------------------------------------------------
extern "C" void kernel_launch(void* const* d_in, const int* in_sizes, int n_in,
                              void* d_out, int out_size) {
    const float* key  = (const float*)d_in[0];
    const float* slot = (const float*)d_in[1];
    float* out = (float*)d_out;

    cudaFuncSetAttribute(k_dots, cudaFuncAttributeMaxDynamicSharedMemorySize, SD_TOT * 4);
    cudaFuncSetAttribute(k_out,  cudaFuncAttributeMaxDynamicSharedMemorySize, SO_TOT * 4);

    k_slot_norm<<<K_, 128>>>(slot);
    k_slot_S<<<K_, K_>>>(slot);
    k_nop<<<1, 32>>>();                     // aligns ncu capture (4th launch) on k_dots
    k_dots<<<dim3(N_ / 128, B_), 256, SD_TOT * 4>>>(key, out);
    k_softmax<<<(B_ * K_) / 8, 256>>>(out);
    k_out<<<dim3(D_ / 128, B_), 256, SO_TOT * 4>>>(slot, key, out);
}

// round 10
// speedup vs baseline: 1.0241x; 1.0241x over previous
#include <cuda_runtime.h>
#include <mma.h>
#include <cstdint>
#include <math.h>

using namespace nvcuda;

constexpr int B_ = 64;
constexpr int N_ = 1024;
constexpr int D_ = 512;
constexpr int K_ = 64;
constexpr int C_ = K_ + N_;                      // 1088
constexpr long OUT_ELEMS = (long)B_ * K_ * D_;
constexpr long DOTS_OFF  = OUT_ELEMS;

#define TEMP_INV (1.0f / 0.07f)

__device__ float g_shat[K_ * D_];                // tf32-rounded normalized slots
__device__ float g_sninv[K_];                    // exact slot inverse norms
__device__ float g_S[K_ * K_];                   // exact slot-slot cosines
__device__ float g_attn[(long)B_ * K_ * C_];     // tf32-rounded attn weights

__device__ __forceinline__ float to_tf32(float x) {
    asm("cvt.rna.tf32.f32 %0, %1;" : "=f"(x) : "f"(x));
    return x;
}
__device__ __forceinline__ uint32_t smem_u32(const void* p) {
    uint32_t a;
    asm("{ .reg .u64 t; cvta.to.shared.u64 t, %1; cvt.u32.u64 %0, t; }" : "=r"(a) : "l"(p));
    return a;
}
__device__ __forceinline__ void cp16(uint32_t dst, const void* src) {
    asm volatile("cp.async.cg.shared.global [%0], [%1], 16;" :: "r"(dst), "l"(src));
}
__device__ __forceinline__ void cp_commit() {
    asm volatile("cp.async.commit_group;" ::: "memory");
}

// ---------------------------------------------------------------------------
// K1: normalize slots -> g_shat (tf32-rounded) + g_sninv (exact)
// ---------------------------------------------------------------------------
__global__ void k_slot_norm(const float* __restrict__ slot) {
    int i = blockIdx.x, t = threadIdx.x;
    float v[4]; float ss = 0.f;
#pragma unroll
    for (int j = 0; j < 4; j++) { v[j] = slot[i * D_ + t + j * 128]; ss += v[j] * v[j]; }
#pragma unroll
    for (int o = 16; o; o >>= 1) ss += __shfl_xor_sync(0xffffffffu, ss, o);
    __shared__ float red[4];
    if ((t & 31) == 0) red[t >> 5] = ss;
    __syncthreads();
    float inv = 1.f / fmaxf(sqrtf(red[0] + red[1] + red[2] + red[3]), 1e-12f);
#pragma unroll
    for (int j = 0; j < 4; j++) g_shat[i * D_ + t + j * 128] = to_tf32(v[j] * inv);
    if (t == 0) g_sninv[i] = inv;
}

// ---------------------------------------------------------------------------
// K2: S = norm(slot) @ norm(slot)^T, exact fp32 from raw slot + sninv
// ---------------------------------------------------------------------------
__global__ void k_slot_S(const float* __restrict__ slot) {
    int i = blockIdx.x, j = threadIdx.x;
    const float4* a = (const float4*)(slot + i * D_);
    const float4* b = (const float4*)(slot + j * D_);
    float acc = 0.f;
#pragma unroll 8
    for (int d = 0; d < D_ / 4; d++) {
        float4 x = a[d], y = b[d];
        acc += x.x * y.x + x.y * y.y + x.z * y.z + x.w * y.w;
    }
    g_S[i * K_ + j] = acc * g_sninv[i] * g_sninv[j];
}

// nop: aligns ncu's captured (4th) launch onto k_dots
__global__ void k_nop() {}

// ---------------------------------------------------------------------------
// K3: dots key-part. CTA: 256 keys x 64 slots, 256 thr / 8 warps,
// warp tile 32(keys)x64(slots) (c[2][4]). cp.async 3-stage, kc=16 (32 chunks).
// 2x work per barrier vs R8; grid 256 = single wave at 2 CTA/SM.
// ---------------------------------------------------------------------------
constexpr int SD_KINV = 0;                        // 256 floats
constexpr int SD_PIPE = 256;
constexpr int SD_ASZ  = 256 * 20;                 // 5120 floats per stage (A)
constexpr int SD_BSZ  = 64 * 20;                  // 1280 floats per stage (B)
constexpr int SD_STG  = SD_ASZ + SD_BSZ;          // 6400
constexpr int SD_CS   = SD_PIPE;                  // epilogue union: 64 x 260 = 16640 <= 19200
constexpr int SD_TOT  = SD_PIPE + 3 * SD_STG;     // 19456 floats = 77824 B

__global__ __launch_bounds__(256, 2) void k_dots(const float* __restrict__ key,
                                                 float* __restrict__ dout) {
    extern __shared__ float smf[];
    const uint32_t sb = smem_u32(smf);
    const int t = threadIdx.x, wid = t >> 5;
    const int b = blockIdx.y, n0blk = blockIdx.x * 256;
    const float* keyb = key + (long)b * N_ * D_;
    const int m0 = wid * 32;          // warp's key offset within 256

    wmma::fragment<wmma::accumulator, 16, 16, 8, float> c[2][4];
#pragma unroll
    for (int i = 0; i < 2; i++)
#pragma unroll
        for (int j = 0; j < 4; j++) wmma::fill_fragment(c[i][j], 0.f);

    float ss = 0.f;                   // thread t owns key row t

    auto issue = [&](int jc) {
        int s = jc % 3;
        uint32_t ab = sb + (SD_PIPE + s * SD_STG) * 4;
        uint32_t bb = ab + SD_ASZ * 4;
        const float* gA = keyb + (long)n0blk * D_ + jc * 16;
        // A: key[256 x 16] = 1024 f4, 4 per thread
#pragma unroll
        for (int q = 0; q < 4; q++) {
            int idx = t + 256 * q, row = idx >> 2, f = idx & 3;
            cp16(ab + (row * 20 + f * 4) * 4, gA + (long)row * D_ + f * 4);
        }
        // B: shat[64 x 16] = 256 f4, 1 per thread
        {
            int row = t >> 2, f = t & 3;
            cp16(bb + (row * 20 + f * 4) * 4, g_shat + row * D_ + jc * 16 + f * 4);
        }
        cp_commit();
    };

    issue(0);
    issue(1);

    for (int jc = 0; jc < 32; jc++) {
        if (jc + 1 < 32) asm volatile("cp.async.wait_group 1;" ::: "memory");
        else             asm volatile("cp.async.wait_group 0;" ::: "memory");
        __syncthreads();
        if (jc + 2 < 32) issue(jc + 2);
        const int s = jc % 3;
        float* As = smf + SD_PIPE + s * SD_STG;
        float* Bs = As + SD_ASZ;
        // norm: thread t owns key row t (raw fp32 in smem, exact)
#pragma unroll
        for (int f = 0; f < 4; f++) {
            float4 v = *(const float4*)(As + t * 20 + f * 4);
            ss += v.x * v.x + v.y * v.y + v.z * v.z + v.w * v.w;
        }
#pragma unroll
        for (int kk = 0; kk < 2; kk++) {
            int k0 = kk * 8;
            wmma::fragment<wmma::matrix_a, 16, 16, 8, wmma::precision::tf32, wmma::row_major> a0, a1;
            wmma::load_matrix_sync(a0, As + (m0)      * 20 + k0, 20);
            wmma::load_matrix_sync(a1, As + (m0 + 16) * 20 + k0, 20);
#pragma unroll
            for (int j = 0; j < 4; j++) {
                wmma::fragment<wmma::matrix_b, 16, 16, 8, wmma::precision::tf32, wmma::col_major> bf;
                wmma::load_matrix_sync(bf, Bs + (16 * j) * 20 + k0, 20);
                wmma::mma_sync(c[0][j], a0, bf, c[0][j]);
                wmma::mma_sync(c[1][j], a1, bf, c[1][j]);
            }
        }
    }

    smf[SD_KINV + t] = 1.f / fmaxf(sqrtf(ss), 1e-12f);
    __syncthreads();     // all consumption done; safe to overwrite pipe with CS

    // C fragments -> smem col-major Cs[slot][key] (ld 260)
#pragma unroll
    for (int i = 0; i < 2; i++)
#pragma unroll
        for (int j = 0; j < 4; j++)
            wmma::store_matrix_sync(smf + SD_CS + (16 * j) * 260 + (m0 + 16 * i),
                                    c[i][j], 260, wmma::mem_col_major);
    __syncthreads();

    // write dots key-part: thread -> slot s = t>>2, key quarter kg = t&3 (64 keys)
    {
        int s = t >> 2, kg = t & 3;
        const float* src = smf + SD_CS + s * 260 + kg * 64;
        const float* kv  = smf + SD_KINV + kg * 64;
        float* dst = dout + DOTS_OFF + (long)b * K_ * C_ + (long)s * C_ + K_ + n0blk + kg * 64;
#pragma unroll
        for (int g = 0; g < 16; g++) {
            float4 w = {src[g * 4 + 0] * kv[g * 4 + 0], src[g * 4 + 1] * kv[g * 4 + 1],
                        src[g * 4 + 2] * kv[g * 4 + 2], src[g * 4 + 3] * kv[g * 4 + 3]};
            *(float4*)(dst + g * 4) = w;
        }
    }
}

// ---------------------------------------------------------------------------
// K4: row softmax with block-causal mask -> g_attn (tf32-rounded);
// slot-slot dots -> output.
// ---------------------------------------------------------------------------
__global__ __launch_bounds__(256) void k_softmax(float* __restrict__ dout) {
    int row  = (blockIdx.x * blockDim.x + threadIdx.x) >> 5;
    int lane = threadIdx.x & 31;
    int b = row >> 6, i = row & 63;

    float* drow = dout + DOTS_OFF + (long)b * K_ * C_ + (long)i * C_;

    float sv[2], kvv[32];
    float m = -1e30f;
#pragma unroll
    for (int r = 0; r < 2; r++) {
        int c = lane + r * 32;
        float s = g_S[i * K_ + c];
        sv[r] = s;
        drow[c] = s;
        if (c < i) m = fmaxf(m, s);
    }
#pragma unroll
    for (int r = 0; r < 32; r++) {
        float v = drow[K_ + lane + r * 32];
        kvv[r] = v;
        m = fmaxf(m, v);
    }
#pragma unroll
    for (int o = 16; o; o >>= 1) m = fmaxf(m, __shfl_xor_sync(0xffffffffu, m, o));

    float sum = 0.f, es[2], ek[32];
#pragma unroll
    for (int r = 0; r < 2; r++) {
        int c = lane + r * 32;
        float x = (c < i) ? __expf((sv[r] - m) * TEMP_INV) : 0.f;
        es[r] = x; sum += x;
    }
#pragma unroll
    for (int r = 0; r < 32; r++) {
        float x = __expf((kvv[r] - m) * TEMP_INV);
        ek[r] = x; sum += x;
    }
#pragma unroll
    for (int o = 16; o; o >>= 1) sum += __shfl_xor_sync(0xffffffffu, sum, o);

    float inv = 1.f / (sum * (1.f + 1e-7f));
    float* at = g_attn + (long)row * C_;
#pragma unroll
    for (int r = 0; r < 2; r++) at[lane + r * 32] = to_tf32(es[r] * inv);
#pragma unroll
    for (int r = 0; r < 32; r++) at[K_ + lane + r * 32] = to_tf32(ek[r] * inv);
}

// ---------------------------------------------------------------------------
// K5: out = attn_n @ [slots; key_b]. CTA: 64 slots x 128 d, 128 thr / 4 warps,
// warp tile 32x64. cp.async 3-stage, kc=32 (34 chunks, half the barriers).
// ---------------------------------------------------------------------------
constexpr int SO_ASZ = 64 * 36;                   // 2304 floats per stage
constexpr int SO_BSZ = 32 * 132;                  // 4224
constexpr int SO_STG = SO_ASZ + SO_BSZ;           // 6528
constexpr int SO_TOT = 3 * SO_STG;                // 19584 floats = 78336 B

__global__ __launch_bounds__(128) void k_out(const float* __restrict__ slot,
                                             const float* __restrict__ key,
                                             float* __restrict__ dout) {
    extern __shared__ float smf[];
    const uint32_t sb = smem_u32(smf);
    const int t = threadIdx.x, wid = t >> 5;
    const int b = blockIdx.y, d0 = blockIdx.x * 128;
    const float* keyb  = key + (long)b * N_ * D_;
    const float* attnb = g_attn + (long)b * K_ * C_;

    const int m0 = (wid & 1) * 32;    // slot offset
    const int n0 = (wid >> 1) * 64;   // d offset

    wmma::fragment<wmma::accumulator, 16, 16, 8, float> c[2][4];
#pragma unroll
    for (int i = 0; i < 2; i++)
#pragma unroll
        for (int j = 0; j < 4; j++) wmma::fill_fragment(c[i][j], 0.f);

    auto issue = [&](int jc) {
        int s = jc % 3;
        uint32_t ab = sb + (s * SO_STG) * 4;
        uint32_t bb = ab + SO_ASZ * 4;
        // A: attn[64 x 32] = 512 f4, 4 per thread (ld 36)
#pragma unroll
        for (int q = 0; q < 4; q++) {
            int idx = t + 128 * q, row = idx >> 3, f = idx & 7;
            cp16(ab + (row * 36 + f * 4) * 4, attnb + (long)row * C_ + jc * 32 + f * 4);
        }
        // B: V[32 x 128] = 1024 f4, 8 per thread (ld 132)
#pragma unroll
        for (int q = 0; q < 8; q++) {
            int idx = t + 128 * q, row = idx >> 5, f = idx & 31;
            int cc = jc * 32 + row;
            const float* src = (cc < K_) ? (slot + (long)cc * D_ + d0 + f * 4)
                                         : (keyb + (long)(cc - K_) * D_ + d0 + f * 4);
            cp16(bb + (row * 132 + f * 4) * 4, src);
        }
        cp_commit();
    };

    issue(0);
    issue(1);

    for (int jc = 0; jc < 34; jc++) {
        if (jc + 1 < 34) asm volatile("cp.async.wait_group 1;" ::: "memory");
        else             asm volatile("cp.async.wait_group 0;" ::: "memory");
        __syncthreads();
        if (jc + 2 < 34) issue(jc + 2);
        const int s = jc % 3;
        float* As = smf + s * SO_STG;
        float* Bs = As + SO_ASZ;
#pragma unroll
        for (int kk = 0; kk < 4; kk++) {
            int k0 = kk * 8;
            wmma::fragment<wmma::matrix_a, 16, 16, 8, wmma::precision::tf32, wmma::row_major> a0, a1;
            wmma::load_matrix_sync(a0, As + (m0)      * 36 + k0, 36);
            wmma::load_matrix_sync(a1, As + (m0 + 16) * 36 + k0, 36);
#pragma unroll
            for (int j = 0; j < 4; j++) {
                wmma::fragment<wmma::matrix_b, 16, 16, 8, wmma::precision::tf32, wmma::row_major> bf;
                wmma::load_matrix_sync(bf, Bs + k0 * 132 + n0 + 16 * j, 132);
                wmma::mma_sync(c[0][j], a0, bf, c[0][j]);
                wmma::mma_sync(c[1][j], a1, bf, c[1][j]);
            }
        }
    }

    // direct global store: out[b][slot][d]
#pragma unroll
    for (int i = 0; i < 2; i++)
#pragma unroll
        for (int j = 0; j < 4; j++) {
            float* gp = dout + (long)b * K_ * D_ + (long)(m0 + 16 * i) * D_ + d0 + n0 + 16 * j;
            wmma::store_matrix_sync(gp, c[i][j], D_, wmma::mem_row_major);
        }
}

// ---------------------------------------------------------------------------
extern "C" void kernel_launch(void* const* d_in, const int* in_sizes, int n_in,
                              void* d_out, int out_size) {
    const float* key  = (const float*)d_in[0];
    const float* slot = (const float*)d_in[1];
    float* out = (float*)d_out;

    cudaFuncSetAttribute(k_dots, cudaFuncAttributeMaxDynamicSharedMemorySize, SD_TOT * 4);
    cudaFuncSetAttribute(k_out,  cudaFuncAttributeMaxDynamicSharedMemorySize, SO_TOT * 4);

    k_slot_norm<<<K_, 128>>>(slot);
    k_slot_S<<<K_, K_>>>(slot);
    k_nop<<<1, 32>>>();                     // aligns ncu capture (4th launch) on k_dots
    k_dots<<<dim3(N_ / 256, B_), 256, SD_TOT * 4>>>(key, out);
    k_softmax<<<(B_ * K_) / 8, 256>>>(out);
    k_out<<<dim3(D_ / 128, B_), 128, SO_TOT * 4>>>(slot, key, out);
}

// round 11
// speedup vs baseline: 1.1046x; 1.0786x over previous
#include <cuda_runtime.h>
#include <cstdint>
#include <math.h>

constexpr int B_ = 64;
constexpr int N_ = 1024;
constexpr int D_ = 512;
constexpr int K_ = 64;
constexpr int C_ = K_ + N_;                      // 1088
constexpr long OUT_ELEMS = (long)B_ * K_ * D_;
constexpr long DOTS_OFF  = OUT_ELEMS;

#define TEMP_INV (1.0f / 0.07f)

__device__ float g_shat[K_ * D_];                // tf32-rounded normalized slots
__device__ float g_sninv[K_];                    // exact slot inverse norms
__device__ float g_S[K_ * K_];                   // exact slot-slot cosines
__device__ float g_attn[(long)B_ * K_ * C_];     // tf32-rounded attn weights

__device__ __forceinline__ float to_tf32(float x) {
    asm("cvt.rna.tf32.f32 %0, %1;" : "=f"(x) : "f"(x));
    return x;
}
__device__ __forceinline__ uint32_t smem_u32(const void* p) {
    uint32_t a;
    asm("{ .reg .u64 t; cvta.to.shared.u64 t, %1; cvt.u32.u64 %0, t; }" : "=r"(a) : "l"(p));
    return a;
}
__device__ __forceinline__ void cp16(uint32_t dst, const void* src) {
    asm volatile("cp.async.cg.shared.global [%0], [%1], 16;" :: "r"(dst), "l"(src));
}
__device__ __forceinline__ void cp_commit() {
    asm volatile("cp.async.commit_group;" ::: "memory");
}
__device__ __forceinline__ void ldsm4(uint32_t* r, uint32_t addr) {
    asm volatile("ldmatrix.sync.aligned.m8n8.x4.shared.b16 {%0,%1,%2,%3}, [%4];"
        : "=r"(r[0]), "=r"(r[1]), "=r"(r[2]), "=r"(r[3]) : "r"(addr));
}
__device__ __forceinline__ void mma8(float* d, const uint32_t* a, const uint32_t* b) {
    asm volatile("mma.sync.aligned.m16n8k8.row.col.f32.tf32.tf32.f32 "
        "{%0,%1,%2,%3}, {%4,%5,%6,%7}, {%8,%9}, {%0,%1,%2,%3};"
        : "+f"(d[0]), "+f"(d[1]), "+f"(d[2]), "+f"(d[3])
        : "r"(a[0]), "r"(a[1]), "r"(a[2]), "r"(a[3]), "r"(b[0]), "r"(b[1]));
}

// ---------------------------------------------------------------------------
// K1: normalize slots -> g_shat (tf32-rounded) + g_sninv (exact)
// ---------------------------------------------------------------------------
__global__ void k_slot_norm(const float* __restrict__ slot) {
    int i = blockIdx.x, t = threadIdx.x;
    float v[4]; float ss = 0.f;
#pragma unroll
    for (int j = 0; j < 4; j++) { v[j] = slot[i * D_ + t + j * 128]; ss += v[j] * v[j]; }
#pragma unroll
    for (int o = 16; o; o >>= 1) ss += __shfl_xor_sync(0xffffffffu, ss, o);
    __shared__ float red[4];
    if ((t & 31) == 0) red[t >> 5] = ss;
    __syncthreads();
    float inv = 1.f / fmaxf(sqrtf(red[0] + red[1] + red[2] + red[3]), 1e-12f);
#pragma unroll
    for (int j = 0; j < 4; j++) g_shat[i * D_ + t + j * 128] = to_tf32(v[j] * inv);
    if (t == 0) g_sninv[i] = inv;
}

// ---------------------------------------------------------------------------
// K2: S = norm(slot) @ norm(slot)^T, exact fp32
// ---------------------------------------------------------------------------
__global__ void k_slot_S(const float* __restrict__ slot) {
    int i = blockIdx.x, j = threadIdx.x;
    const float4* a = (const float4*)(slot + i * D_);
    const float4* b = (const float4*)(slot + j * D_);
    float acc = 0.f;
#pragma unroll 8
    for (int d = 0; d < D_ / 4; d++) {
        float4 x = a[d], y = b[d];
        acc += x.x * y.x + x.y * y.y + x.z * y.z + x.w * y.w;
    }
    g_S[i * K_ + j] = acc * g_sninv[i] * g_sninv[j];
}

// nop: aligns ncu's captured (4th) launch onto k_dots
__global__ void k_nop() {}

// ---------------------------------------------------------------------------
// K3: dots key-part via raw mma.sync + ldmatrix. CTA: 256 keys x 64 slots,
// 256 thr / 8 warps, warp tile 32(keys) x 64(slots). cp.async 3-stage, kc=16.
// Direct global epilogue (no smem C pass). Fused key norms.
// ---------------------------------------------------------------------------
constexpr int SD_KINV = 0;                        // 256 floats
constexpr int SD_PIPE = 256;
constexpr int SD_ASZ  = 256 * 20;                 // A stage (floats)
constexpr int SD_BSZ  = 64 * 20;                  // B stage
constexpr int SD_STG  = SD_ASZ + SD_BSZ;          // 6400
constexpr int SD_TOT  = SD_PIPE + 3 * SD_STG;     // 19456 floats = 77824 B

__global__ __launch_bounds__(256, 2) void k_dots(const float* __restrict__ key,
                                                 float* __restrict__ dout) {
    extern __shared__ float smf[];
    const uint32_t sb = smem_u32(smf);
    const int t = threadIdx.x, wid = t >> 5, l = t & 31;
    const int b = blockIdx.y, n0blk = blockIdx.x * 256;
    const float* keyb = key + (long)b * N_ * D_;
    const int m0 = wid * 32;

    // lane-invariant ldmatrix offsets (in floats), ld = 20
    const int laneA = ((((l >> 3) & 1) * 8 + (l & 7)) * 20) + (l >> 4) * 4;
    const int laneB = (((l >> 4) * 8 + (l & 7)) * 20) + ((l >> 3) & 1) * 4;

    float c[2][8][4];
#pragma unroll
    for (int i = 0; i < 2; i++)
#pragma unroll
        for (int j = 0; j < 8; j++)
#pragma unroll
            for (int k = 0; k < 4; k++) c[i][j][k] = 0.f;

    float ss = 0.f;

    auto issue = [&](int jc) {
        int s = jc % 3;
        uint32_t ab = sb + (SD_PIPE + s * SD_STG) * 4;
        uint32_t bb = ab + SD_ASZ * 4;
        const float* gA = keyb + (long)n0blk * D_ + jc * 16;
#pragma unroll
        for (int q = 0; q < 4; q++) {
            int idx = t + 256 * q, row = idx >> 2, f = idx & 3;
            cp16(ab + (row * 20 + f * 4) * 4, gA + (long)row * D_ + f * 4);
        }
        {
            int row = t >> 2, f = t & 3;
            cp16(bb + (row * 20 + f * 4) * 4, g_shat + row * D_ + jc * 16 + f * 4);
        }
        cp_commit();
    };

    issue(0);
    issue(1);

    for (int jc = 0; jc < 32; jc++) {
        if (jc + 1 < 32) asm volatile("cp.async.wait_group 1;" ::: "memory");
        else             asm volatile("cp.async.wait_group 0;" ::: "memory");
        __syncthreads();
        if (jc + 2 < 32) issue(jc + 2);
        const int s = jc % 3;
        const float* As = smf + SD_PIPE + s * SD_STG;
        uint32_t a4 = sb + (SD_PIPE + s * SD_STG) * 4;
        uint32_t b4 = a4 + SD_ASZ * 4;
        // norm: thread t owns key row t (raw fp32 in smem, exact)
#pragma unroll
        for (int f = 0; f < 4; f++) {
            float4 v = *(const float4*)(As + t * 20 + f * 4);
            ss += v.x * v.x + v.y * v.y + v.z * v.z + v.w * v.w;
        }
#pragma unroll
        for (int k8 = 0; k8 < 16; k8 += 8) {
            uint32_t a[2][4], bf[4][4];
            ldsm4(a[0], a4 + ((m0)      * 20 + k8 + laneA) * 4);
            ldsm4(a[1], a4 + ((m0 + 16) * 20 + k8 + laneA) * 4);
#pragma unroll
            for (int p = 0; p < 4; p++)
                ldsm4(bf[p], b4 + ((16 * p) * 20 + k8 + laneB) * 4);
#pragma unroll
            for (int mb = 0; mb < 2; mb++)
#pragma unroll
                for (int p = 0; p < 4; p++) {
                    mma8(c[mb][2 * p],     a[mb], &bf[p][0]);
                    mma8(c[mb][2 * p + 1], a[mb], &bf[p][2]);
                }
        }
    }

    smf[SD_KINV + t] = 1.f / fmaxf(sqrtf(ss), 1e-12f);
    __syncthreads();

    // epilogue: direct global store of dots[slot][key] with kinv scaling
    {
        int g = l >> 2, tq = l & 3;
        float* base = dout + DOTS_OFF + (long)b * K_ * C_ + K_;
#pragma unroll
        for (int mb = 0; mb < 2; mb++) {
            int kl0 = m0 + 16 * mb + g, kl1 = kl0 + 8;
            float kv0 = smf[SD_KINV + kl0], kv1 = smf[SD_KINV + kl1];
            long key0 = n0blk + kl0, key1 = n0blk + kl1;
#pragma unroll
            for (int nb = 0; nb < 8; nb++) {
                int s0 = nb * 8 + 2 * tq;
                base[(long)s0 * C_ + key0]       = c[mb][nb][0] * kv0;
                base[(long)(s0 + 1) * C_ + key0] = c[mb][nb][1] * kv0;
                base[(long)s0 * C_ + key1]       = c[mb][nb][2] * kv1;
                base[(long)(s0 + 1) * C_ + key1] = c[mb][nb][3] * kv1;
            }
        }
    }
}

// ---------------------------------------------------------------------------
// K4: row softmax with block-causal mask -> g_attn (tf32-rounded);
// slot-slot dots -> output.
// ---------------------------------------------------------------------------
__global__ __launch_bounds__(256) void k_softmax(float* __restrict__ dout) {
    int row  = (blockIdx.x * blockDim.x + threadIdx.x) >> 5;
    int lane = threadIdx.x & 31;
    int b = row >> 6, i = row & 63;

    float* drow = dout + DOTS_OFF + (long)b * K_ * C_ + (long)i * C_;

    float sv[2], kvv[32];
    float m = -1e30f;
#pragma unroll
    for (int r = 0; r < 2; r++) {
        int c = lane + r * 32;
        float s = g_S[i * K_ + c];
        sv[r] = s;
        drow[c] = s;
        if (c < i) m = fmaxf(m, s);
    }
#pragma unroll
    for (int r = 0; r < 32; r++) {
        float v = drow[K_ + lane + r * 32];
        kvv[r] = v;
        m = fmaxf(m, v);
    }
#pragma unroll
    for (int o = 16; o; o >>= 1) m = fmaxf(m, __shfl_xor_sync(0xffffffffu, m, o));

    float sum = 0.f, es[2], ek[32];
#pragma unroll
    for (int r = 0; r < 2; r++) {
        int c = lane + r * 32;
        float x = (c < i) ? __expf((sv[r] - m) * TEMP_INV) : 0.f;
        es[r] = x; sum += x;
    }
#pragma unroll
    for (int r = 0; r < 32; r++) {
        float x = __expf((kvv[r] - m) * TEMP_INV);
        ek[r] = x; sum += x;
    }
#pragma unroll
    for (int o = 16; o; o >>= 1) sum += __shfl_xor_sync(0xffffffffu, sum, o);

    float inv = 1.f / (sum * (1.f + 1e-7f));
    float* at = g_attn + (long)row * C_;
#pragma unroll
    for (int r = 0; r < 2; r++) at[lane + r * 32] = to_tf32(es[r] * inv);
#pragma unroll
    for (int r = 0; r < 32; r++) at[K_ + lane + r * 32] = to_tf32(ek[r] * inv);
}

// ---------------------------------------------------------------------------
// K5: out = attn_n @ [slots; key_b] via raw mma.sync + ldmatrix.
// CTA: 64 slots x 128 d, 256 thr / 8 warps, warp tile 32x32.
// A = attn (cp.async 3-stage). B = V^T staged via reg-prefetched LDG + STS
// transpose into 2 buffers ([d][c], ld 20). kc=16, 68 chunks.
// ---------------------------------------------------------------------------
constexpr int SO_A   = 0;                         // 3 x 64*20 = 3840 floats
constexpr int SO_B   = 3 * 64 * 20;               // 2 x 128*20 = 5120
constexpr int SO_TOT = SO_B + 2 * 128 * 20;       // 8960 floats = 35840 B

__global__ __launch_bounds__(256) void k_out(const float* __restrict__ slot,
                                             const float* __restrict__ key,
                                             float* __restrict__ dout) {
    extern __shared__ float smf[];
    const uint32_t sb = smem_u32(smf);
    const int t = threadIdx.x, wid = t >> 5, l = t & 31;
    const int b = blockIdx.y, d0 = blockIdx.x * 128;
    const float* keyb  = key + (long)b * N_ * D_;
    const float* attnb = g_attn + (long)b * K_ * C_;

    const int m0 = (wid & 1) * 32;    // slot offset
    const int n0 = (wid >> 1) * 32;   // d offset (0,32,64,96)

    const int laneA = ((((l >> 3) & 1) * 8 + (l & 7)) * 20) + (l >> 4) * 4;
    const int laneB = (((l >> 4) * 8 + (l & 7)) * 20) + ((l >> 3) & 1) * 4;

    float c[2][4][4];
#pragma unroll
    for (int i = 0; i < 2; i++)
#pragma unroll
        for (int j = 0; j < 4; j++)
#pragma unroll
            for (int k = 0; k < 4; k++) c[i][j][k] = 0.f;

    float4 vr[2];

    auto issueA = [&](int jc) {
        int row = t >> 2, f = t & 3;
        cp16(sb + ((SO_A + (jc % 3) * 1280) + (row * 20 + f * 4)) * 4,
             attnb + (long)row * C_ + jc * 16 + f * 4);
        cp_commit();
    };
    auto ldgB = [&](int jc) {
#pragma unroll
        for (int q = 0; q < 2; q++) {
            int idx = t + 256 * q, row = idx >> 5, dc = idx & 31;
            int cc = jc * 16 + row;
            const float* src = (cc < K_) ? (slot + (long)cc * D_ + d0 + dc * 4)
                                         : (keyb + (long)(cc - K_) * D_ + d0 + dc * 4);
            vr[q] = *(const float4*)src;
        }
    };
    auto stsB = [&](int buf) {
        float* vt = smf + SO_B + buf * 2560;
#pragma unroll
        for (int q = 0; q < 2; q++) {
            int idx = t + 256 * q, row = idx >> 5, dc = idx & 31;
            vt[(dc * 4 + 0) * 20 + row] = vr[q].x;
            vt[(dc * 4 + 1) * 20 + row] = vr[q].y;
            vt[(dc * 4 + 2) * 20 + row] = vr[q].z;
            vt[(dc * 4 + 3) * 20 + row] = vr[q].w;
        }
    };

    issueA(0);
    issueA(1);
    ldgB(0); stsB(0);
    ldgB(1);

    for (int jc = 0; jc < 68; jc++) {
        if (jc + 1 < 68) asm volatile("cp.async.wait_group 1;" ::: "memory");
        else             asm volatile("cp.async.wait_group 0;" ::: "memory");
        __syncthreads();
        if (jc + 2 < 68) issueA(jc + 2);
        if (jc + 1 < 68) stsB((jc + 1) & 1);
        if (jc + 2 < 68) ldgB(jc + 2);
        uint32_t a4 = sb + (SO_A + (jc % 3) * 1280) * 4;
        uint32_t b4 = sb + (SO_B + (jc & 1) * 2560) * 4;
#pragma unroll
        for (int k8 = 0; k8 < 16; k8 += 8) {
            uint32_t a[2][4], bf[2][4];
            ldsm4(a[0], a4 + ((m0)      * 20 + k8 + laneA) * 4);
            ldsm4(a[1], a4 + ((m0 + 16) * 20 + k8 + laneA) * 4);
            ldsm4(bf[0], b4 + ((n0)      * 20 + k8 + laneB) * 4);
            ldsm4(bf[1], b4 + ((n0 + 16) * 20 + k8 + laneB) * 4);
#pragma unroll
            for (int mb = 0; mb < 2; mb++)
#pragma unroll
                for (int p = 0; p < 2; p++) {
                    mma8(c[mb][2 * p],     a[mb], &bf[p][0]);
                    mma8(c[mb][2 * p + 1], a[mb], &bf[p][2]);
                }
        }
    }

    // epilogue: direct global store out[b][slot][d]
    {
        int g = l >> 2, tq = l & 3;
#pragma unroll
        for (int mb = 0; mb < 2; mb++) {
            int s0 = m0 + 16 * mb + g, s1 = s0 + 8;
#pragma unroll
            for (int nb = 0; nb < 4; nb++) {
                int d = d0 + n0 + nb * 8 + 2 * tq;
                float2 w0 = {c[mb][nb][0], c[mb][nb][1]};
                float2 w1 = {c[mb][nb][2], c[mb][nb][3]};
                *(float2*)(dout + (long)b * K_ * D_ + (long)s0 * D_ + d) = w0;
                *(float2*)(dout + (long)b * K_ * D_ + (long)s1 * D_ + d) = w1;
            }
        }
    }
}

// ---------------------------------------------------------------------------
extern "C" void kernel_launch(void* const* d_in, const int* in_sizes, int n_in,
                              void* d_out, int out_size) {
    const float* key  = (const float*)d_in[0];
    const float* slot = (const float*)d_in[1];
    float* out = (float*)d_out;

    cudaFuncSetAttribute(k_dots, cudaFuncAttributeMaxDynamicSharedMemorySize, SD_TOT * 4);
    cudaFuncSetAttribute(k_out,  cudaFuncAttributeMaxDynamicSharedMemorySize, SO_TOT * 4);

    k_slot_norm<<<K_, 128>>>(slot);
    k_slot_S<<<K_, K_>>>(slot);
    k_nop<<<1, 32>>>();                     // aligns ncu capture (4th launch) on k_dots
    k_dots<<<dim3(N_ / 256, B_), 256, SD_TOT * 4>>>(key, out);
    k_softmax<<<(B_ * K_) / 8, 256>>>(out);
    k_out<<<dim3(D_ / 128, B_), 256, SO_TOT * 4>>>(slot, key, out);
}

// round 12
// speedup vs baseline: 1.7762x; 1.6080x over previous
#include <cuda_runtime.h>
#include <cstdint>
#include <math.h>

constexpr int B_ = 64;
constexpr int N_ = 1024;
constexpr int D_ = 512;
constexpr int K_ = 64;
constexpr int C_ = K_ + N_;                      // 1088
constexpr long OUT_ELEMS = (long)B_ * K_ * D_;
constexpr long DOTS_OFF  = OUT_ELEMS;

#define TEMP_INV (1.0f / 0.07f)

__device__ float g_shat[K_ * D_];                // tf32-rounded normalized slots
__device__ float g_S[K_ * K_];                   // exact slot-slot cosines
__device__ float g_attn[(long)B_ * K_ * C_];     // tf32-rounded attn weights

__device__ __forceinline__ float to_tf32(float x) {
    asm("cvt.rna.tf32.f32 %0, %1;" : "=f"(x) : "f"(x));
    return x;
}
__device__ __forceinline__ uint32_t smem_u32(const void* p) {
    uint32_t a;
    asm("{ .reg .u64 t; cvta.to.shared.u64 t, %1; cvt.u32.u64 %0, t; }" : "=r"(a) : "l"(p));
    return a;
}
__device__ __forceinline__ void cp16(uint32_t dst, const void* src) {
    asm volatile("cp.async.cg.shared.global [%0], [%1], 16;" :: "r"(dst), "l"(src));
}
__device__ __forceinline__ void cp_commit() {
    asm volatile("cp.async.commit_group;" ::: "memory");
}
__device__ __forceinline__ void ldsm4(uint32_t* r, uint32_t addr) {
    asm volatile("ldmatrix.sync.aligned.m8n8.x4.shared.b16 {%0,%1,%2,%3}, [%4];"
        : "=r"(r[0]), "=r"(r[1]), "=r"(r[2]), "=r"(r[3]) : "r"(addr));
}
__device__ __forceinline__ void mma8(float* d, const uint32_t* a, const uint32_t* b) {
    asm volatile("mma.sync.aligned.m16n8k8.row.col.f32.tf32.tf32.f32 "
        "{%0,%1,%2,%3}, {%4,%5,%6,%7}, {%8,%9}, {%0,%1,%2,%3};"
        : "+f"(d[0]), "+f"(d[1]), "+f"(d[2]), "+f"(d[3])
        : "r"(a[0]), "r"(a[1]), "r"(a[2]), "r"(a[3]), "r"(b[0]), "r"(b[1]));
}

// ---------------------------------------------------------------------------
// K1: merged slot prep. Block i: all dots with slot_i, norms, S row, shat row.
// (Merging K1+K2 also places k_out at ncu's captured 4th launch.)
// ---------------------------------------------------------------------------
__global__ void k_prep(const float* __restrict__ slot) {
    int i = blockIdx.x, j = threadIdx.x;   // 64 threads
    const float4* a = (const float4*)(slot + i * D_);
    const float4* b = (const float4*)(slot + j * D_);
    float dot = 0.f, nj = 0.f;
#pragma unroll 8
    for (int d = 0; d < D_ / 4; d++) {
        float4 x = a[d], y = b[d];
        dot += x.x * y.x + x.y * y.y + x.z * y.z + x.w * y.w;
        nj  += y.x * y.x + y.y * y.y + y.z * y.z + y.w * y.w;
    }
    __shared__ float n[64];
    n[j] = nj;
    __syncthreads();
    float inv_j = 1.f / fmaxf(sqrtf(nj),   1e-12f);
    float inv_i = 1.f / fmaxf(sqrtf(n[i]), 1e-12f);
    g_S[i * K_ + j] = dot * inv_i * inv_j;
#pragma unroll
    for (int q = 0; q < 8; q++) {
        int d = j + 64 * q;
        g_shat[i * D_ + d] = to_tf32(slot[i * D_ + d] * inv_i);
    }
}

// ---------------------------------------------------------------------------
// K2: dots key-part via raw mma.sync + ldmatrix. CTA: 256 keys x 64 slots,
// 256 thr / 8 warps, warp tile 32(keys) x 64(slots). cp.async 3-stage, kc=16.
// Direct global epilogue. Fused key norms.  (unchanged from R11 — proven)
// ---------------------------------------------------------------------------
constexpr int SD_KINV = 0;                        // 256 floats
constexpr int SD_PIPE = 256;
constexpr int SD_ASZ  = 256 * 20;                 // A stage (floats)
constexpr int SD_BSZ  = 64 * 20;                  // B stage
constexpr int SD_STG  = SD_ASZ + SD_BSZ;          // 6400
constexpr int SD_TOT  = SD_PIPE + 3 * SD_STG;     // 19456 floats = 77824 B

__global__ __launch_bounds__(256, 2) void k_dots(const float* __restrict__ key,
                                                 float* __restrict__ dout) {
    extern __shared__ float smf[];
    const uint32_t sb = smem_u32(smf);
    const int t = threadIdx.x, wid = t >> 5, l = t & 31;
    const int b = blockIdx.y, n0blk = blockIdx.x * 256;
    const float* keyb = key + (long)b * N_ * D_;
    const int m0 = wid * 32;

    const int laneA = ((((l >> 3) & 1) * 8 + (l & 7)) * 20) + (l >> 4) * 4;
    const int laneB = (((l >> 4) * 8 + (l & 7)) * 20) + ((l >> 3) & 1) * 4;

    float c[2][8][4];
#pragma unroll
    for (int i = 0; i < 2; i++)
#pragma unroll
        for (int j = 0; j < 8; j++)
#pragma unroll
            for (int k = 0; k < 4; k++) c[i][j][k] = 0.f;

    float ss = 0.f;

    auto issue = [&](int jc) {
        int s = jc % 3;
        uint32_t ab = sb + (SD_PIPE + s * SD_STG) * 4;
        uint32_t bb = ab + SD_ASZ * 4;
        const float* gA = keyb + (long)n0blk * D_ + jc * 16;
#pragma unroll
        for (int q = 0; q < 4; q++) {
            int idx = t + 256 * q, row = idx >> 2, f = idx & 3;
            cp16(ab + (row * 20 + f * 4) * 4, gA + (long)row * D_ + f * 4);
        }
        {
            int row = t >> 2, f = t & 3;
            cp16(bb + (row * 20 + f * 4) * 4, g_shat + row * D_ + jc * 16 + f * 4);
        }
        cp_commit();
    };

    issue(0);
    issue(1);

    for (int jc = 0; jc < 32; jc++) {
        if (jc + 1 < 32) asm volatile("cp.async.wait_group 1;" ::: "memory");
        else             asm volatile("cp.async.wait_group 0;" ::: "memory");
        __syncthreads();
        if (jc + 2 < 32) issue(jc + 2);
        const int s = jc % 3;
        const float* As = smf + SD_PIPE + s * SD_STG;
        uint32_t a4 = sb + (SD_PIPE + s * SD_STG) * 4;
        uint32_t b4 = a4 + SD_ASZ * 4;
#pragma unroll
        for (int f = 0; f < 4; f++) {
            float4 v = *(const float4*)(As + t * 20 + f * 4);
            ss += v.x * v.x + v.y * v.y + v.z * v.z + v.w * v.w;
        }
#pragma unroll
        for (int k8 = 0; k8 < 16; k8 += 8) {
            uint32_t a[2][4], bf[4][4];
            ldsm4(a[0], a4 + ((m0)      * 20 + k8 + laneA) * 4);
            ldsm4(a[1], a4 + ((m0 + 16) * 20 + k8 + laneA) * 4);
#pragma unroll
            for (int p = 0; p < 4; p++)
                ldsm4(bf[p], b4 + ((16 * p) * 20 + k8 + laneB) * 4);
#pragma unroll
            for (int mb = 0; mb < 2; mb++)
#pragma unroll
                for (int p = 0; p < 4; p++) {
                    mma8(c[mb][2 * p],     a[mb], &bf[p][0]);
                    mma8(c[mb][2 * p + 1], a[mb], &bf[p][2]);
                }
        }
    }

    smf[SD_KINV + t] = 1.f / fmaxf(sqrtf(ss), 1e-12f);
    __syncthreads();

    {
        int g = l >> 2, tq = l & 3;
        float* base = dout + DOTS_OFF + (long)b * K_ * C_ + K_;
#pragma unroll
        for (int mb = 0; mb < 2; mb++) {
            int kl0 = m0 + 16 * mb + g, kl1 = kl0 + 8;
            float kv0 = smf[SD_KINV + kl0], kv1 = smf[SD_KINV + kl1];
            long key0 = n0blk + kl0, key1 = n0blk + kl1;
#pragma unroll
            for (int nb = 0; nb < 8; nb++) {
                int s0 = nb * 8 + 2 * tq;
                base[(long)s0 * C_ + key0]       = c[mb][nb][0] * kv0;
                base[(long)(s0 + 1) * C_ + key0] = c[mb][nb][1] * kv0;
                base[(long)s0 * C_ + key1]       = c[mb][nb][2] * kv1;
                base[(long)(s0 + 1) * C_ + key1] = c[mb][nb][3] * kv1;
            }
        }
    }
}

// ---------------------------------------------------------------------------
// K3: row softmax with block-causal mask -> g_attn (tf32-rounded);
// slot-slot dots -> output.
// ---------------------------------------------------------------------------
__global__ __launch_bounds__(256) void k_softmax(float* __restrict__ dout) {
    int row  = (blockIdx.x * blockDim.x + threadIdx.x) >> 5;
    int lane = threadIdx.x & 31;
    int b = row >> 6, i = row & 63;

    float* drow = dout + DOTS_OFF + (long)b * K_ * C_ + (long)i * C_;

    float sv[2], kvv[32];
    float m = -1e30f;
#pragma unroll
    for (int r = 0; r < 2; r++) {
        int c = lane + r * 32;
        float s = g_S[i * K_ + c];
        sv[r] = s;
        drow[c] = s;
        if (c < i) m = fmaxf(m, s);
    }
#pragma unroll
    for (int r = 0; r < 32; r++) {
        float v = drow[K_ + lane + r * 32];
        kvv[r] = v;
        m = fmaxf(m, v);
    }
#pragma unroll
    for (int o = 16; o; o >>= 1) m = fmaxf(m, __shfl_xor_sync(0xffffffffu, m, o));

    float sum = 0.f, es[2], ek[32];
#pragma unroll
    for (int r = 0; r < 2; r++) {
        int c = lane + r * 32;
        float x = (c < i) ? __expf((sv[r] - m) * TEMP_INV) : 0.f;
        es[r] = x; sum += x;
    }
#pragma unroll
    for (int r = 0; r < 32; r++) {
        float x = __expf((kvv[r] - m) * TEMP_INV);
        ek[r] = x; sum += x;
    }
#pragma unroll
    for (int o = 16; o; o >>= 1) sum += __shfl_xor_sync(0xffffffffu, sum, o);

    float inv = 1.f / (sum * (1.f + 1e-7f));
    float* at = g_attn + (long)row * C_;
#pragma unroll
    for (int r = 0; r < 2; r++) at[lane + r * 32] = to_tf32(es[r] * inv);
#pragma unroll
    for (int r = 0; r < 32; r++) at[K_ + lane + r * 32] = to_tf32(ek[r] * inv);
}

// ---------------------------------------------------------------------------
// K4: out = attn_n @ [slots; key_b]. CTA: 64 slots x 128 d, 256 thr / 8 warps,
// warp tile 32 slots x 32 d. A: cp.async+ldmatrix ([s][c] ld 20).
// B: cp.async row-major [c][d] ld 136 (NO transpose); frags via scalar LDS
// at (k=l&3, n=l>>2) — bank-conflict-free. kc=16, 68 chunks, 3 stages.
// ---------------------------------------------------------------------------
constexpr int SO_ASZ = 64 * 20;                   // 1280 floats per stage
constexpr int SO_BSZ = 16 * 136;                  // 2176
constexpr int SO_STG = SO_ASZ + SO_BSZ;           // 3456
constexpr int SO_TOT = 3 * SO_STG;                // 10368 floats = 41472 B

__global__ __launch_bounds__(256) void k_out(const float* __restrict__ slot,
                                             const float* __restrict__ key,
                                             float* __restrict__ dout) {
    extern __shared__ float smf[];
    const uint32_t sb = smem_u32(smf);
    const int t = threadIdx.x, wid = t >> 5, l = t & 31;
    const int b = blockIdx.y, d0 = blockIdx.x * 128;
    const float* keyb  = key + (long)b * N_ * D_;
    const float* attnb = g_attn + (long)b * K_ * C_;

    const int m0 = (wid & 1) * 32;    // slot offset
    const int n0 = (wid >> 1) * 32;   // d offset (0,32,64,96)

    const int laneA = ((((l >> 3) & 1) * 8 + (l & 7)) * 20) + (l >> 4) * 4;
    const int bK = l & 3, bN = l >> 2;   // B frag coords

    float c[2][4][4];
#pragma unroll
    for (int i = 0; i < 2; i++)
#pragma unroll
        for (int j = 0; j < 4; j++)
#pragma unroll
            for (int k = 0; k < 4; k++) c[i][j][k] = 0.f;

    auto issue = [&](int jc) {
        int s = jc % 3;
        uint32_t ab = sb + (s * SO_STG) * 4;
        uint32_t bb = ab + SO_ASZ * 4;
        // A: attn[64 x 16] = 256 f4, 1 per thread
        {
            int row = t >> 2, f = t & 3;
            cp16(ab + (row * 20 + f * 4) * 4, attnb + (long)row * C_ + jc * 16 + f * 4);
        }
        // B: V[16 x 128] row-major ld 136 = 512 f4, 2 per thread
#pragma unroll
        for (int q = 0; q < 2; q++) {
            int idx = t + 256 * q, row = idx >> 5, dc = idx & 31;
            int cc = jc * 16 + row;
            const float* src = (cc < K_) ? (slot + (long)cc * D_ + d0 + dc * 4)
                                         : (keyb + (long)(cc - K_) * D_ + d0 + dc * 4);
            cp16(bb + (row * 136 + dc * 4) * 4, src);
        }
        cp_commit();
    };

    issue(0);
    issue(1);

    for (int jc = 0; jc < 68; jc++) {
        if (jc + 1 < 68) asm volatile("cp.async.wait_group 1;" ::: "memory");
        else             asm volatile("cp.async.wait_group 0;" ::: "memory");
        __syncthreads();
        if (jc + 2 < 68) issue(jc + 2);
        const int s = jc % 3;
        uint32_t a4 = sb + (s * SO_STG) * 4;
        const float* Bs = smf + s * SO_STG + SO_ASZ;
#pragma unroll
        for (int k8 = 0; k8 < 16; k8 += 8) {
            uint32_t a[2][4];
            ldsm4(a[0], a4 + ((m0)      * 20 + k8 + laneA) * 4);
            ldsm4(a[1], a4 + ((m0 + 16) * 20 + k8 + laneA) * 4);
#pragma unroll
            for (int p = 0; p < 4; p++) {
                int np = n0 + p * 8;
                uint32_t b2[2];
                b2[0] = __float_as_uint(Bs[(k8 + bK)     * 136 + np + bN]);
                b2[1] = __float_as_uint(Bs[(k8 + bK + 4) * 136 + np + bN]);
                mma8(c[0][p], a[0], b2);
                mma8(c[1][p], a[1], b2);
            }
        }
    }

    // epilogue: direct global store out[b][slot][d]
    {
        int g = l >> 2, tq = l & 3;
#pragma unroll
        for (int mb = 0; mb < 2; mb++) {
            int s0 = m0 + 16 * mb + g, s1 = s0 + 8;
#pragma unroll
            for (int nb = 0; nb < 4; nb++) {
                int d = d0 + n0 + nb * 8 + 2 * tq;
                float2 w0 = {c[mb][nb][0], c[mb][nb][1]};
                float2 w1 = {c[mb][nb][2], c[mb][nb][3]};
                *(float2*)(dout + (long)b * K_ * D_ + (long)s0 * D_ + d) = w0;
                *(float2*)(dout + (long)b * K_ * D_ + (long)s1 * D_ + d) = w1;
            }
        }
    }
}

// ---------------------------------------------------------------------------
extern "C" void kernel_launch(void* const* d_in, const int* in_sizes, int n_in,
                              void* d_out, int out_size) {
    const float* key  = (const float*)d_in[0];
    const float* slot = (const float*)d_in[1];
    float* out = (float*)d_out;

    cudaFuncSetAttribute(k_dots, cudaFuncAttributeMaxDynamicSharedMemorySize, SD_TOT * 4);
    cudaFuncSetAttribute(k_out,  cudaFuncAttributeMaxDynamicSharedMemorySize, SO_TOT * 4);

    k_prep<<<K_, K_>>>(slot);
    k_dots<<<dim3(N_ / 256, B_), 256, SD_TOT * 4>>>(key, out);
    k_softmax<<<(B_ * K_) / 8, 256>>>(out);
    k_out<<<dim3(D_ / 128, B_), 256, SO_TOT * 4>>>(slot, key, out);   // 4th: ncu target
}